// round 1
// baseline (speedup 1.0000x reference)
#include <cuda_runtime.h>
#include <math.h>

#define D_MODEL 768
#define D_HID   3072
#define NE      8
#define NTOK    2048

#define BM 128
#define BN 128
#define BK 16
#define TM 8
#define TN 8

// ---- scratch (static device globals; no allocation allowed) ----
__device__ int   g_cnt[NE];
__device__ int   g_rows[NE * NTOK];
__device__ float g_wt[NE * NTOK];
__device__ float g_hid[(size_t)NE * NTOK * D_HID];   // ~201 MB worst-case arena

// ---------------------------------------------------------------
// Zero output + expert counters
// ---------------------------------------------------------------
__global__ void init_kernel(float* __restrict__ out) {
    int idx = blockIdx.x * blockDim.x + threadIdx.x;
    if (idx < NE) g_cnt[idx] = 0;
    if (idx < NTOK * D_MODEL) out[idx] = 0.0f;
}

// ---------------------------------------------------------------
// Router: logits = x @ gate_w, softmax, top-2, normalized weights,
// append token to the two chosen experts' lists.
// One block (128 threads) per token.
// ---------------------------------------------------------------
__global__ void router_kernel(const float* __restrict__ x,
                              const float* __restrict__ gw) {
    int n   = blockIdx.x;
    int tid = threadIdx.x;

    float acc[NE];
#pragma unroll
    for (int e = 0; e < NE; e++) acc[e] = 0.0f;

    const float* xr = x + (size_t)n * D_MODEL;
    for (int d = tid; d < D_MODEL; d += 128) {
        float xv = xr[d];
#pragma unroll
        for (int e = 0; e < NE; e++) acc[e] += xv * gw[d * NE + e];
    }

    __shared__ float red[NE][128];
#pragma unroll
    for (int e = 0; e < NE; e++) red[e][tid] = acc[e];
    __syncthreads();

    for (int s = 64; s > 0; s >>= 1) {
        if (tid < s) {
#pragma unroll
            for (int e = 0; e < NE; e++) red[e][tid] += red[e][tid + s];
        }
        __syncthreads();
    }

    if (tid == 0) {
        float l[NE];
        float mx = -1e30f;
#pragma unroll
        for (int e = 0; e < NE; e++) { l[e] = red[e][0]; mx = fmaxf(mx, l[e]); }
        float p[NE];
#pragma unroll
        for (int e = 0; e < NE; e++) p[e] = expf(l[e] - mx);

        // top-1 (first max on ties, matching lax.top_k)
        int   i1 = 0; float p1 = p[0];
#pragma unroll
        for (int e = 1; e < NE; e++) if (p[e] > p1) { p1 = p[e]; i1 = e; }
        // top-2
        int   i2 = -1; float p2 = -1.0f;
#pragma unroll
        for (int e = 0; e < NE; e++)
            if (e != i1 && p[e] > p2) { p2 = p[e]; i2 = e; }

        float inv = 1.0f / (p1 + p2);
        int pos1 = atomicAdd(&g_cnt[i1], 1);
        g_rows[i1 * NTOK + pos1] = n;
        g_wt  [i1 * NTOK + pos1] = p1 * inv;
        int pos2 = atomicAdd(&g_cnt[i2], 1);
        g_rows[i2 * NTOK + pos2] = n;
        g_wt  [i2 * NTOK + pos2] = p2 * inv;
    }
}

// ---------------------------------------------------------------
// GEMM1: H[e] = gelu( Xg[e] @ W1[e] + b1[e] )
// A gathered via g_rows; 128x128x16 tiles, 8x8 per thread.
// ---------------------------------------------------------------
__global__ void __launch_bounds__(256)
gemm1_kernel(const float* __restrict__ x,
             const float* __restrict__ w1,
             const float* __restrict__ bias1) {
    int e   = blockIdx.z;
    int cnt = g_cnt[e];
    int m0  = blockIdx.y * BM;
    if (m0 >= cnt) return;
    int n0  = blockIdx.x * BN;

    const float* Bmat = w1 + (size_t)e * D_MODEL * D_HID;
    const int*   rows = g_rows + e * NTOK;

    __shared__ float As[BK][BM];
    __shared__ float Bs[BK][BN];

    int tid = threadIdx.x;
    int tx = tid & 15;
    int ty = tid >> 4;

    // A-load mapping: 2048 elems, 8 per thread
    int arow = tid >> 1;             // 0..127
    int acg  = (tid & 1) * 8;        // 0 or 8
    int gm   = m0 + arow;
    int tok  = rows[gm < cnt ? gm : (cnt - 1)];
    const float* aptr = x + (size_t)tok * D_MODEL;

    // B-load mapping
    int brow = tid >> 4;             // 0..15
    int bcol = (tid & 15) * 8;       // 0..120

    float acc[TM][TN];
#pragma unroll
    for (int i = 0; i < TM; i++)
#pragma unroll
        for (int j = 0; j < TN; j++) acc[i][j] = 0.0f;

    for (int k0 = 0; k0 < D_MODEL; k0 += BK) {
        float4 a0 = *(const float4*)(aptr + k0 + acg);
        float4 a1 = *(const float4*)(aptr + k0 + acg + 4);
        As[acg + 0][arow] = a0.x; As[acg + 1][arow] = a0.y;
        As[acg + 2][arow] = a0.z; As[acg + 3][arow] = a0.w;
        As[acg + 4][arow] = a1.x; As[acg + 5][arow] = a1.y;
        As[acg + 6][arow] = a1.z; As[acg + 7][arow] = a1.w;

        const float* bp = Bmat + (size_t)(k0 + brow) * D_HID + n0 + bcol;
        *(float4*)&Bs[brow][bcol]     = *(const float4*)bp;
        *(float4*)&Bs[brow][bcol + 4] = *(const float4*)(bp + 4);
        __syncthreads();

#pragma unroll
        for (int k = 0; k < BK; k++) {
            float av[TM], bv[TN];
            float4 t0 = *(const float4*)&As[k][ty * TM];
            float4 t1 = *(const float4*)&As[k][ty * TM + 4];
            av[0]=t0.x; av[1]=t0.y; av[2]=t0.z; av[3]=t0.w;
            av[4]=t1.x; av[5]=t1.y; av[6]=t1.z; av[7]=t1.w;
            float4 u0 = *(const float4*)&Bs[k][tx * TN];
            float4 u1 = *(const float4*)&Bs[k][tx * TN + 4];
            bv[0]=u0.x; bv[1]=u0.y; bv[2]=u0.z; bv[3]=u0.w;
            bv[4]=u1.x; bv[5]=u1.y; bv[6]=u1.z; bv[7]=u1.w;
#pragma unroll
            for (int i = 0; i < TM; i++)
#pragma unroll
                for (int j = 0; j < TN; j++)
                    acc[i][j] += av[i] * bv[j];
        }
        __syncthreads();
    }

    float* hb = g_hid + (size_t)e * NTOK * D_HID;
#pragma unroll
    for (int i = 0; i < TM; i++) {
        int m = m0 + ty * TM + i;
        if (m < cnt) {
#pragma unroll
            for (int j = 0; j < TN; j++) {
                int n = n0 + tx * TN + j;
                float v = acc[i][j] + bias1[e * D_HID + n];
                v = 0.5f * v * (1.0f + erff(v * 0.70710678118654752f));
                hb[(size_t)m * D_HID + n] = v;
            }
        }
    }
}

// ---------------------------------------------------------------
// GEMM2: out[tok] += wt * ( H[e] @ W2[e] + b2[e] )
// ---------------------------------------------------------------
__global__ void __launch_bounds__(256)
gemm2_kernel(const float* __restrict__ w2,
             const float* __restrict__ bias2,
             float* __restrict__ out) {
    int e   = blockIdx.z;
    int cnt = g_cnt[e];
    int m0  = blockIdx.y * BM;
    if (m0 >= cnt) return;
    int n0  = blockIdx.x * BN;

    const float* Amat = g_hid + (size_t)e * NTOK * D_HID;
    const float* Bmat = w2 + (size_t)e * D_HID * D_MODEL;

    __shared__ float As[BK][BM];
    __shared__ float Bs[BK][BN];

    int tid = threadIdx.x;
    int tx = tid & 15;
    int ty = tid >> 4;

    int arow = tid >> 1;
    int acg  = (tid & 1) * 8;
    int gm   = m0 + arow;
    int am   = gm < cnt ? gm : (cnt - 1);
    const float* aptr = Amat + (size_t)am * D_HID;

    int brow = tid >> 4;
    int bcol = (tid & 15) * 8;

    float acc[TM][TN];
#pragma unroll
    for (int i = 0; i < TM; i++)
#pragma unroll
        for (int j = 0; j < TN; j++) acc[i][j] = 0.0f;

    for (int k0 = 0; k0 < D_HID; k0 += BK) {
        float4 a0 = *(const float4*)(aptr + k0 + acg);
        float4 a1 = *(const float4*)(aptr + k0 + acg + 4);
        As[acg + 0][arow] = a0.x; As[acg + 1][arow] = a0.y;
        As[acg + 2][arow] = a0.z; As[acg + 3][arow] = a0.w;
        As[acg + 4][arow] = a1.x; As[acg + 5][arow] = a1.y;
        As[acg + 6][arow] = a1.z; As[acg + 7][arow] = a1.w;

        const float* bp = Bmat + (size_t)(k0 + brow) * D_MODEL + n0 + bcol;
        *(float4*)&Bs[brow][bcol]     = *(const float4*)bp;
        *(float4*)&Bs[brow][bcol + 4] = *(const float4*)(bp + 4);
        __syncthreads();

#pragma unroll
        for (int k = 0; k < BK; k++) {
            float av[TM], bv[TN];
            float4 t0 = *(const float4*)&As[k][ty * TM];
            float4 t1 = *(const float4*)&As[k][ty * TM + 4];
            av[0]=t0.x; av[1]=t0.y; av[2]=t0.z; av[3]=t0.w;
            av[4]=t1.x; av[5]=t1.y; av[6]=t1.z; av[7]=t1.w;
            float4 u0 = *(const float4*)&Bs[k][tx * TN];
            float4 u1 = *(const float4*)&Bs[k][tx * TN + 4];
            bv[0]=u0.x; bv[1]=u0.y; bv[2]=u0.z; bv[3]=u0.w;
            bv[4]=u1.x; bv[5]=u1.y; bv[6]=u1.z; bv[7]=u1.w;
#pragma unroll
            for (int i = 0; i < TM; i++)
#pragma unroll
                for (int j = 0; j < TN; j++)
                    acc[i][j] += av[i] * bv[j];
        }
        __syncthreads();
    }

    const int* rows = g_rows + e * NTOK;
    const float* wts = g_wt + e * NTOK;
#pragma unroll
    for (int i = 0; i < TM; i++) {
        int m = m0 + ty * TM + i;
        if (m < cnt) {
            int   tok = rows[m];
            float wt  = wts[m];
            float* orow = out + (size_t)tok * D_MODEL;
#pragma unroll
            for (int j = 0; j < TN; j++) {
                int n = n0 + tx * TN + j;
                float v = acc[i][j] + bias2[e * D_MODEL + n];
                atomicAdd(&orow[n], wt * v);
            }
        }
    }
}

// ---------------------------------------------------------------
extern "C" void kernel_launch(void* const* d_in, const int* in_sizes, int n_in,
                              void* d_out, int out_size) {
    const float* x  = (const float*)d_in[0];
    const float* gw = (const float*)d_in[1];
    const float* w1 = (const float*)d_in[2];
    const float* b1 = (const float*)d_in[3];
    const float* w2 = (const float*)d_in[4];
    const float* b2 = (const float*)d_in[5];
    float* out = (float*)d_out;

    init_kernel<<<(NTOK * D_MODEL + 255) / 256, 256>>>(out);
    router_kernel<<<NTOK, 128>>>(x, gw);
    gemm1_kernel<<<dim3(D_HID / BN, NTOK / BM, NE), 256>>>(x, w1, b1);
    gemm2_kernel<<<dim3(D_MODEL / BN, NTOK / BM, NE), 256>>>(w2, b2, out);
}

// round 8
// speedup vs baseline: 3.0663x; 3.0663x over previous
#include <cuda_runtime.h>
#include <math.h>
#include <stdint.h>

#define D_MODEL 768
#define D_HID   3072
#define NE      8
#define NTOK    2048

#define BM 128
#define BN 128
#define BK 32
#define NC1 (D_MODEL/BK)   // 24
#define NC2 (D_HID/BK)     // 96

#define ASTRIDE 36
#define BSTRIDE 136
#define ASZ (BM*ASTRIDE)          // 4608 floats
#define BSZ (BK*BSTRIDE)          // 4352 floats
#define SM_FLOATS (2*ASZ + 2*BSZ) // 17920 floats
#define SMEM_BYTES (SM_FLOATS*4 + 640)

// ---------------- device scratch (static; no allocation allowed) ------------
__device__ int   g_cnt[NE];
__device__ int   g_rows[NE*NTOK];
__device__ float g_wt[NE*NTOK];
__device__ float g_hid[(size_t)NE*NTOK*D_HID];   // fp32 hidden arena (~201 MB)

// ---------------- helpers ---------------------------------------------------
__device__ __forceinline__ float cvt_tf32(float x) {
    float r;
    asm("cvt.rna.tf32.f32 %0, %1;" : "=f"(r) : "f"(x));
    return r;
}

__device__ __forceinline__ void mma_tf32(float c[4],
                                         uint32_t a0, uint32_t a1, uint32_t a2, uint32_t a3,
                                         uint32_t b0, uint32_t b1) {
    asm volatile("mma.sync.aligned.m16n8k8.row.col.f32.tf32.tf32.f32 "
        "{%0,%1,%2,%3}, {%4,%5,%6,%7}, {%8,%9}, {%0,%1,%2,%3};"
        : "+f"(c[0]), "+f"(c[1]), "+f"(c[2]), "+f"(c[3])
        : "r"(a0), "r"(a1), "r"(a2), "r"(a3), "r"(b0), "r"(b1));
}

__device__ __forceinline__ float gelu_erf(float v) {
    return 0.5f * v * (1.0f + erff(v * 0.70710678118654752f));
}

// ---------------------------------------------------------------
// init: zero output + expert counters
// ---------------------------------------------------------------
__global__ void init_kernel(float* __restrict__ out) {
    int idx = blockIdx.x * blockDim.x + threadIdx.x;
    if (idx < NE) g_cnt[idx] = 0;
    if (idx < NTOK * D_MODEL) out[idx] = 0.0f;
}

// ---------------------------------------------------------------
// Router: softmax top-2, normalized weights, expert lists
// ---------------------------------------------------------------
__global__ void router_kernel(const float* __restrict__ x,
                              const float* __restrict__ gw) {
    int n   = blockIdx.x;
    int tid = threadIdx.x;
    float acc[NE];
#pragma unroll
    for (int e = 0; e < NE; e++) acc[e] = 0.0f;
    const float* xr = x + (size_t)n * D_MODEL;
    for (int d = tid; d < D_MODEL; d += 128) {
        float xv = xr[d];
#pragma unroll
        for (int e = 0; e < NE; e++) acc[e] += xv * gw[d * NE + e];
    }
    __shared__ float red[NE][128];
#pragma unroll
    for (int e = 0; e < NE; e++) red[e][tid] = acc[e];
    __syncthreads();
    for (int s = 64; s > 0; s >>= 1) {
        if (tid < s) {
#pragma unroll
            for (int e = 0; e < NE; e++) red[e][tid] += red[e][tid + s];
        }
        __syncthreads();
    }
    if (tid == 0) {
        float l[NE]; float mx = -1e30f;
#pragma unroll
        for (int e = 0; e < NE; e++) { l[e] = red[e][0]; mx = fmaxf(mx, l[e]); }
        float p[NE];
#pragma unroll
        for (int e = 0; e < NE; e++) p[e] = expf(l[e] - mx);
        int i1 = 0; float p1 = p[0];
#pragma unroll
        for (int e = 1; e < NE; e++) if (p[e] > p1) { p1 = p[e]; i1 = e; }
        int i2 = -1; float p2 = -1.0f;
#pragma unroll
        for (int e = 0; e < NE; e++) if (e != i1 && p[e] > p2) { p2 = p[e]; i2 = e; }
        float inv = 1.0f / (p1 + p2);
        int pos1 = atomicAdd(&g_cnt[i1], 1);
        g_rows[i1 * NTOK + pos1] = n;
        g_wt  [i1 * NTOK + pos1] = p1 * inv;
        int pos2 = atomicAdd(&g_cnt[i2], 1);
        g_rows[i2 * NTOK + pos2] = n;
        g_wt  [i2 * NTOK + pos2] = p2 * inv;
    }
}

// ---------------------------------------------------------------
// GEMM1 (mma.sync tf32): H[e] = gelu(Xg[e] @ W1[e] + b1), fp32 hidden out
// ---------------------------------------------------------------
__global__ void __launch_bounds__(256)
moe_gemm1(const float* __restrict__ x,
          const float* __restrict__ w1,
          const float* __restrict__ b1) {
    extern __shared__ float sm[];
    int e = blockIdx.z;
    int cnt = g_cnt[e];
    int m0 = blockIdx.y * BM;
    if (m0 >= cnt) return;
    int n0 = blockIdx.x * BN;
    int tid = threadIdx.x, lane = tid & 31, wid = tid >> 5;
    int wm = wid >> 2, wn = wid & 3;

    int* srows = (int*)(sm + SM_FLOATS);
    if (tid < 128) {
        int gm = m0 + tid;
        srows[tid] = g_rows[e * NTOK + (gm < cnt ? gm : cnt - 1)];
    }
    __syncthreads();

    const float* W = w1 + (size_t)e * D_MODEL * D_HID;
    int arow = tid >> 3;       // rows arow + t*32
    int acg  = (tid & 7) * 4;
    int brow = tid >> 5;       // rows brow + t*8
    int bcg  = (tid & 31) * 4;

    const float* aptr[4];
#pragma unroll
    for (int t = 0; t < 4; t++)
        aptr[t] = x + (size_t)srows[arow + t * 32] * D_MODEL + acg;

    float4 ra[4], rb[4];
    float acc[4][4][4];
#pragma unroll
    for (int mi = 0; mi < 4; mi++)
#pragma unroll
        for (int ni = 0; ni < 4; ni++)
#pragma unroll
            for (int q = 0; q < 4; q++) acc[mi][ni][q] = 0.0f;

    auto LDG = [&](int c) {
        int k0 = c * BK;
#pragma unroll
        for (int t = 0; t < 4; t++) ra[t] = *(const float4*)(aptr[t] + k0);
#pragma unroll
        for (int t = 0; t < 4; t++)
            rb[t] = *(const float4*)(W + (size_t)(k0 + brow + t * 8) * D_HID + n0 + bcg);
    };
    auto STS = [&](int s) {
        float* A = sm + s * ASZ;
        float* B = sm + 2 * ASZ + s * BSZ;
#pragma unroll
        for (int t = 0; t < 4; t++) {
            float4 v = make_float4(cvt_tf32(ra[t].x), cvt_tf32(ra[t].y),
                                   cvt_tf32(ra[t].z), cvt_tf32(ra[t].w));
            *(float4*)(A + (arow + t * 32) * ASTRIDE + acg) = v;
        }
#pragma unroll
        for (int t = 0; t < 4; t++) {
            float4 v = make_float4(cvt_tf32(rb[t].x), cvt_tf32(rb[t].y),
                                   cvt_tf32(rb[t].z), cvt_tf32(rb[t].w));
            *(float4*)(B + (brow + t * 8) * BSTRIDE + bcg) = v;
        }
    };
    auto COMPUTE = [&](int s) {
        const float* A = sm + s * ASZ;
        const float* B = sm + 2 * ASZ + s * BSZ;
        const float* pa = A + (wm * 64 + (lane >> 2)) * ASTRIDE + (lane & 3);
        const float* pb = B + (lane & 3) * BSTRIDE + wn * 32 + (lane >> 2);
#pragma unroll
        for (int ks = 0; ks < 4; ks++) {
            uint32_t af[4][4], bf[4][2];
#pragma unroll
            for (int mi = 0; mi < 4; mi++) {
                const float* p = pa + mi * 16 * ASTRIDE + ks * 8;
                af[mi][0] = __float_as_uint(p[0]);
                af[mi][1] = __float_as_uint(p[8 * ASTRIDE]);
                af[mi][2] = __float_as_uint(p[4]);
                af[mi][3] = __float_as_uint(p[8 * ASTRIDE + 4]);
            }
#pragma unroll
            for (int ni = 0; ni < 4; ni++) {
                const float* p = pb + ni * 8 + ks * 8 * BSTRIDE;
                bf[ni][0] = __float_as_uint(p[0]);
                bf[ni][1] = __float_as_uint(p[4 * BSTRIDE]);
            }
#pragma unroll
            for (int mi = 0; mi < 4; mi++)
#pragma unroll
                for (int ni = 0; ni < 4; ni++)
                    mma_tf32(acc[mi][ni], af[mi][0], af[mi][1], af[mi][2], af[mi][3],
                             bf[ni][0], bf[ni][1]);
        }
    };

    LDG(0); STS(0); __syncthreads();
    for (int c = 0; c < NC1; c++) {
        if (c + 1 < NC1) LDG(c + 1);
        COMPUTE(c & 1);
        if (c + 1 < NC1) STS((c + 1) & 1);
        __syncthreads();
    }

    float* H = g_hid + ((size_t)e * NTOK + m0) * D_HID;
    const float* bias = b1 + (size_t)e * D_HID;
#pragma unroll
    for (int mi = 0; mi < 4; mi++) {
        int r0 = wm * 64 + mi * 16 + (lane >> 2);
#pragma unroll
        for (int half = 0; half < 2; half++) {
            int r = r0 + half * 8;
            if (m0 + r < cnt) {
                float* hr = H + (size_t)r * D_HID;
#pragma unroll
                for (int ni = 0; ni < 4; ni++) {
                    int n = n0 + wn * 32 + ni * 8 + 2 * (lane & 3);
                    float v0 = acc[mi][ni][half * 2 + 0] + bias[n];
                    float v1 = acc[mi][ni][half * 2 + 1] + bias[n + 1];
                    *(float2*)(hr + n) = make_float2(gelu_erf(v0), gelu_erf(v1));
                }
            }
        }
    }
}

// ---------------------------------------------------------------
// GEMM2 (mma.sync tf32): out[tok] += wt * (H[e] @ W2[e] + b2)
// ---------------------------------------------------------------
__global__ void __launch_bounds__(256)
moe_gemm2(const float* __restrict__ w2,
          const float* __restrict__ b2,
          float* __restrict__ out) {
    extern __shared__ float sm[];
    int e = blockIdx.z;
    int cnt = g_cnt[e];
    int m0 = blockIdx.y * BM;
    if (m0 >= cnt) return;
    int n0 = blockIdx.x * BN;
    int tid = threadIdx.x, lane = tid & 31, wid = tid >> 5;
    int wm = wid >> 2, wn = wid & 3;

    int* srows = (int*)(sm + SM_FLOATS);
    if (tid < 128) {
        int gm = m0 + tid;
        srows[tid] = g_rows[e * NTOK + (gm < cnt ? gm : cnt - 1)];
    }
    __syncthreads();

    const float* W = w2 + (size_t)e * D_HID * D_MODEL;
    const float* H = g_hid + (size_t)e * NTOK * D_HID;
    int arow = tid >> 3;
    int acg  = (tid & 7) * 4;
    int brow = tid >> 5;
    int bcg  = (tid & 31) * 4;

    const float* aptr[4];
#pragma unroll
    for (int t = 0; t < 4; t++) {
        int gm = m0 + arow + t * 32;
        int rm = gm < cnt ? gm : cnt - 1;
        aptr[t] = H + (size_t)rm * D_HID + acg;
    }

    float4 ra[4], rb[4];
    float acc[4][4][4];
#pragma unroll
    for (int mi = 0; mi < 4; mi++)
#pragma unroll
        for (int ni = 0; ni < 4; ni++)
#pragma unroll
            for (int q = 0; q < 4; q++) acc[mi][ni][q] = 0.0f;

    auto LDG = [&](int c) {
        int k0 = c * BK;
#pragma unroll
        for (int t = 0; t < 4; t++) ra[t] = *(const float4*)(aptr[t] + k0);
#pragma unroll
        for (int t = 0; t < 4; t++)
            rb[t] = *(const float4*)(W + (size_t)(k0 + brow + t * 8) * D_MODEL + n0 + bcg);
    };
    auto STS = [&](int s) {
        float* A = sm + s * ASZ;
        float* B = sm + 2 * ASZ + s * BSZ;
#pragma unroll
        for (int t = 0; t < 4; t++) {
            float4 v = make_float4(cvt_tf32(ra[t].x), cvt_tf32(ra[t].y),
                                   cvt_tf32(ra[t].z), cvt_tf32(ra[t].w));
            *(float4*)(A + (arow + t * 32) * ASTRIDE + acg) = v;
        }
#pragma unroll
        for (int t = 0; t < 4; t++) {
            float4 v = make_float4(cvt_tf32(rb[t].x), cvt_tf32(rb[t].y),
                                   cvt_tf32(rb[t].z), cvt_tf32(rb[t].w));
            *(float4*)(B + (brow + t * 8) * BSTRIDE + bcg) = v;
        }
    };
    auto COMPUTE = [&](int s) {
        const float* A = sm + s * ASZ;
        const float* B = sm + 2 * ASZ + s * BSZ;
        const float* pa = A + (wm * 64 + (lane >> 2)) * ASTRIDE + (lane & 3);
        const float* pb = B + (lane & 3) * BSTRIDE + wn * 32 + (lane >> 2);
#pragma unroll
        for (int ks = 0; ks < 4; ks++) {
            uint32_t af[4][4], bf[4][2];
#pragma unroll
            for (int mi = 0; mi < 4; mi++) {
                const float* p = pa + mi * 16 * ASTRIDE + ks * 8;
                af[mi][0] = __float_as_uint(p[0]);
                af[mi][1] = __float_as_uint(p[8 * ASTRIDE]);
                af[mi][2] = __float_as_uint(p[4]);
                af[mi][3] = __float_as_uint(p[8 * ASTRIDE + 4]);
            }
#pragma unroll
            for (int ni = 0; ni < 4; ni++) {
                const float* p = pb + ni * 8 + ks * 8 * BSTRIDE;
                bf[ni][0] = __float_as_uint(p[0]);
                bf[ni][1] = __float_as_uint(p[4 * BSTRIDE]);
            }
#pragma unroll
            for (int mi = 0; mi < 4; mi++)
#pragma unroll
                for (int ni = 0; ni < 4; ni++)
                    mma_tf32(acc[mi][ni], af[mi][0], af[mi][1], af[mi][2], af[mi][3],
                             bf[ni][0], bf[ni][1]);
        }
    };

    LDG(0); STS(0); __syncthreads();
    for (int c = 0; c < NC2; c++) {
        if (c + 1 < NC2) LDG(c + 1);
        COMPUTE(c & 1);
        if (c + 1 < NC2) STS((c + 1) & 1);
        __syncthreads();
    }

    const float* bias = b2 + (size_t)e * D_MODEL;
#pragma unroll
    for (int mi = 0; mi < 4; mi++) {
        int r0 = wm * 64 + mi * 16 + (lane >> 2);
#pragma unroll
        for (int half = 0; half < 2; half++) {
            int r = r0 + half * 8;
            int m = m0 + r;
            if (m < cnt) {
                int   tok = srows[r];
                float wt  = g_wt[e * NTOK + m];
                float* orow = out + (size_t)tok * D_MODEL;
#pragma unroll
                for (int ni = 0; ni < 4; ni++) {
                    int n = n0 + wn * 32 + ni * 8 + 2 * (lane & 3);
                    float v0 = (acc[mi][ni][half * 2 + 0] + bias[n])     * wt;
                    float v1 = (acc[mi][ni][half * 2 + 1] + bias[n + 1]) * wt;
                    atomicAdd(orow + n,     v0);
                    atomicAdd(orow + n + 1, v1);
                }
            }
        }
    }
}

// ---------------------------------------------------------------
extern "C" void kernel_launch(void* const* d_in, const int* in_sizes, int n_in,
                              void* d_out, int out_size) {
    const float* x  = (const float*)d_in[0];
    const float* gw = (const float*)d_in[1];
    const float* w1 = (const float*)d_in[2];
    const float* b1 = (const float*)d_in[3];
    const float* w2 = (const float*)d_in[4];
    const float* b2 = (const float*)d_in[5];
    float* out = (float*)d_out;

    cudaFuncSetAttribute(moe_gemm1, cudaFuncAttributeMaxDynamicSharedMemorySize, SMEM_BYTES);
    cudaFuncSetAttribute(moe_gemm2, cudaFuncAttributeMaxDynamicSharedMemorySize, SMEM_BYTES);

    init_kernel<<<(NTOK * D_MODEL + 255) / 256, 256>>>(out);
    router_kernel<<<NTOK, 128>>>(x, gw);
    moe_gemm1<<<dim3(D_HID / BN, NTOK / BM, NE), 256, SMEM_BYTES>>>(x, w1, b1);
    moe_gemm2<<<dim3(D_MODEL / BN, NTOK / BM, NE), 256, SMEM_BYTES>>>(w2, b2, out);
}